// round 1
// baseline (speedup 1.0000x reference)
#include <cuda_runtime.h>
#include <math.h>

#define BB 32
#define NN 96
#define FF 128
#define NBI (BB*NN)

// ---------------- scratch (device globals; no allocations) ----------------
__device__ float g_sim [BB*NN*NN];
__device__ float g_cm  [BB*NN*NN];
__device__ float g_f1  [BB*NN*NN];
__device__ float g_f2  [BB*NN*NN];
__device__ float g_nat [NBI];
__device__ float g_csum[NBI];
__device__ float g_A   [NBI*FF];
__device__ float g_ypre[NBI*FF];
__device__ float g_y2  [NBI*FF];

// ---------------- K0: sim, cosine-cutoff*mask, neighbor counts ----------------
__global__ void k_prep(const float* __restrict__ r, const float* __restrict__ mask) {
    int bi  = blockIdx.x;          // b*N + i
    int j   = threadIdx.x;         // 0..95
    int idx = bi * NN + j;
    float rv = r[idx];
    float m  = mask[idx];
    g_sim[idx] = expf(-rv) * m;    // exp(-5*r/CUTOFF) with CUTOFF=5
    float c = 0.0f;
    if (rv < 5.0f)
        c = 0.5f * (cosf(rv * 0.62831853071795864769f) + 1.0f) * m;  // pi/5
    g_cm[idx] = c;

    // reduce mask over j (3 warps)
    float s = m;
    #pragma unroll
    for (int o = 16; o > 0; o >>= 1) s += __shfl_down_sync(0xffffffffu, s, o);
    __shared__ float ws[3];
    if ((j & 31) == 0) ws[j >> 5] = s;
    __syncthreads();
    if (j == 0) g_nat[bi] = fmaxf(ws[0] + ws[1] + ws[2], 1.0f);
}

// ---------------- K1/K2: hop powers  fout[b,i,k] = (fin[b,i,:]·sim[b,:,k]) / n[b,i]
// 8 output rows per block so each block streams sim[b] once for 8 rows.
__global__ void k_hop(const float* __restrict__ fin, float* __restrict__ fout) {
    int blk = blockIdx.x;                 // b*(N/8) + itile
    int b   = blk / (NN / 8);
    int i0  = (blk % (NN / 8)) * 8;
    int k   = threadIdx.x;                // 0..95
    __shared__ float rows[8][NN];
    #pragma unroll
    for (int rr = 0; rr < 8; rr++)
        rows[rr][k] = fin[(b * NN + i0 + rr) * NN + k];
    __syncthreads();

    const float* sb = g_sim + b * NN * NN;
    float acc[8];
    #pragma unroll
    for (int rr = 0; rr < 8; rr++) acc[rr] = 0.0f;

    #pragma unroll 4
    for (int j = 0; j < NN; j++) {
        float sv = sb[j * NN + k];        // coalesced
        #pragma unroll
        for (int rr = 0; rr < 8; rr++)
            acc[rr] = fmaf(rows[rr][j], sv, acc[rr]);   // rows[][] is warp-broadcast
    }
    #pragma unroll
    for (int rr = 0; rr < 8; rr++)
        fout[(b * NN + i0 + rr) * NN + k] = acc[rr] / g_nat[b * NN + i0 + rr];
}

// ---------------- K3: A[b,i,f] = sum_j Cm * ssp(f0*w0 + f1*w1 + f2*w2 + fb1)
__global__ void k_accS(const float* __restrict__ fw1, const float* __restrict__ fb1) {
    int bi = blockIdx.x;
    int f  = threadIdx.x;                 // 0..127
    float w0 = fw1[f], w1 = fw1[FF + f], w2 = fw1[2 * FF + f], b1 = fb1[f];

    __shared__ float s0[NN], s1[NN], s2[NN], sc[NN];
    if (f < NN) {
        int idx = bi * NN + f;
        s0[f] = g_sim[idx]; s1[f] = g_f1[idx]; s2[f] = g_f2[idx]; sc[f] = g_cm[idx];
    }
    __syncthreads();

    float acc = 0.0f, csum = 0.0f;
    for (int j = 0; j < NN; j++) {
        float c = sc[j];
        csum += c;
        if (c != 0.0f) {                  // uniform across block: cheap skip (~47%)
            float z  = fmaf(s2[j], w2, fmaf(s1[j], w1, fmaf(s0[j], w0, b1)));
            float e  = __expf(-fabsf(z));
            float sp = fmaxf(z, 0.0f) + __logf(1.0f + e);   // softplus, stable
            acc = fmaf(c, sp - 0.69314718055994530942f, acc);
        }
    }
    g_A[bi * FF + f] = acc;
    if (f == 0) g_csum[bi] = csum;
}

// ---------------- K4..K6: 3072x128 @ 128x128 GEMMs with fused epilogues
// MODE 0: out = A@W                          (y_pre = x @ W_in2f)
// MODE 1: out = (A@W + fb2*csum[row]) * extra[row,g]   (Wsum * y_pre)
// MODE 2: out = ssp(A@W + b_out)             (final activation)
template <int MODE>
__global__ void k_gemm(const float* __restrict__ Ain, const float* __restrict__ Wm,
                       const float* __restrict__ bias, const float* __restrict__ extra,
                       const float* __restrict__ csum, float* __restrict__ out) {
    __shared__ float sW[32 * FF];   // K-chunk of weights
    __shared__ float sA[16 * FF];   // 16 rows of A
    int row0 = blockIdx.x * 16;
    int t    = threadIdx.x;         // 256
    for (int k = t; k < 16 * FF; k += 256) sA[k] = Ain[row0 * FF + k];

    int g     = t & (FF - 1);
    int rbase = (t >> 7) * 8;
    float acc[8];
    #pragma unroll
    for (int rr = 0; rr < 8; rr++) acc[rr] = 0.0f;

    for (int kb = 0; kb < FF; kb += 32) {
        __syncthreads();
        for (int k = t; k < 32 * FF; k += 256) sW[k] = Wm[kb * FF + k];
        __syncthreads();
        #pragma unroll
        for (int ff = 0; ff < 32; ff++) {
            float wv = sW[ff * FF + g];
            #pragma unroll
            for (int rr = 0; rr < 8; rr++)
                acc[rr] = fmaf(sA[(rbase + rr) * FF + kb + ff], wv, acc[rr]);
        }
    }

    #pragma unroll
    for (int rr = 0; rr < 8; rr++) {
        int   orow = row0 + rbase + rr;
        float v    = acc[rr];
        if (MODE == 1) {
            v = fmaf(bias[g], csum[orow], v);   // fb2 scaled by sum_j Cm (fb2==0 here, exact anyway)
            v *= extra[orow * FF + g];
        } else if (MODE == 2) {
            v += bias[g];
            float e = expf(-fabsf(v));
            v = fmaxf(v, 0.0f) + log1pf(e) - 0.69314718055994530942f;
        }
        out[orow * FF + g] = v;
    }
}

// ---------------- launch ----------------
extern "C" void kernel_launch(void* const* d_in, const int* in_sizes, int n_in,
                              void* d_out, int out_size) {
    const float* x      = (const float*)d_in[0];
    const float* r      = (const float*)d_in[1];
    // d_in[2] = neighbors (int32) — unused by this forward variant
    const float* mask   = (const float*)d_in[3];
    const float* W_in2f = (const float*)d_in[4];
    const float* fw1    = (const float*)d_in[5];
    const float* fb1    = (const float*)d_in[6];
    const float* fw2    = (const float*)d_in[7];
    const float* fb2    = (const float*)d_in[8];
    const float* W_out  = (const float*)d_in[9];
    const float* b_out  = (const float*)d_in[10];
    float* out = (float*)d_out;

    float *sim, *f1, *f2, *A, *ypre, *y2, *csum;
    cudaGetSymbolAddress((void**)&sim,  g_sim);
    cudaGetSymbolAddress((void**)&f1,   g_f1);
    cudaGetSymbolAddress((void**)&f2,   g_f2);
    cudaGetSymbolAddress((void**)&A,    g_A);
    cudaGetSymbolAddress((void**)&ypre, g_ypre);
    cudaGetSymbolAddress((void**)&y2,   g_y2);
    cudaGetSymbolAddress((void**)&csum, g_csum);

    k_prep<<<NBI, NN>>>(r, mask);
    k_hop <<<BB * (NN / 8), NN>>>(sim, f1);
    k_hop <<<BB * (NN / 8), NN>>>(f1, f2);
    k_accS<<<NBI, FF>>>(fw1, fb1);
    k_gemm<0><<<NBI / 16, 256>>>(x,  W_in2f, nullptr, nullptr, nullptr, ypre);
    k_gemm<1><<<NBI / 16, 256>>>(A,  fw2,    fb2,     ypre,    csum,    y2);
    k_gemm<2><<<NBI / 16, 256>>>(y2, W_out,  b_out,   nullptr, nullptr, out);
}

// round 2
// speedup vs baseline: 1.2433x; 1.2433x over previous
#include <cuda_runtime.h>
#include <math.h>

#define BB 32
#define NN 96
#define FF 128
#define NBI (BB*NN)
#define LN2f   0.69314718055994530942f
#define LOG2Ef 1.44269504088896340736f

// ---------------- scratch (device globals; no allocations) ----------------
__device__ float g_sim [BB*NN*NN];
__device__ float g_cm  [BB*NN*NN];
__device__ float g_nat [NBI];
__device__ float g_csum[NBI];
__device__ float g_A   [NBI*FF];

// ================= K0: sim, cosine-cutoff*mask, neighbor counts =================
__global__ void k_prep(const float* __restrict__ r, const float* __restrict__ mask) {
    int bi  = blockIdx.x;          // b*N + i
    int j   = threadIdx.x;         // 0..95
    int idx = bi * NN + j;
    float rv = r[idx];
    float m  = mask[idx];
    g_sim[idx] = expf(-rv) * m;    // exp(-5*r/CUTOFF), CUTOFF=5
    float c = 0.0f;
    if (rv < 5.0f)
        c = 0.5f * (cosf(rv * 0.62831853071795864769f) + 1.0f) * m;  // pi/5
    g_cm[idx] = c;

    float s = m;
    #pragma unroll
    for (int o = 16; o > 0; o >>= 1) s += __shfl_down_sync(0xffffffffu, s, o);
    __shared__ float ws[3];
    if ((j & 31) == 0) ws[j >> 5] = s;
    __syncthreads();
    if (j == 0) g_nat[bi] = fmaxf(ws[0] + ws[1] + ws[2], 1.0f);
}

// ================= K1: fused hop1 + hop2 + accS =================
// Block owns 8 rows (b, i0..i0+7). Computes f1, f2 for its rows in shared,
// then A[row,f] = sum_j cm * ssp(sim*w0 + f1*w1 + f2*w2 + b1) over the
// ballot-compacted active-j list. Nothing but A/csum touches global.
__global__ __launch_bounds__(128) void k_hopacc(const float* __restrict__ fw1,
                                                const float* __restrict__ fb1) {
    __shared__ __align__(16) float r0T[NN][8];   // sim rows, transposed [j][rr]
    __shared__ __align__(16) float r1T[NN][8];   // f1 rows
    __shared__ __align__(16) float r2T[NN][8];   // f2 rows
    __shared__ float cwT[NN][8];                 // cm rows
    __shared__ float4 packed[8][NN];             // compacted {s0,s1,s2,cm*ln2}
    __shared__ float invn[8], csum_s[8];
    __shared__ int   cnt_s[8];

    int b  = blockIdx.x / (NN / 8);
    int i0 = (blockIdx.x % (NN / 8)) * 8;
    int t  = threadIdx.x;                        // 0..127
    const float* simb = g_sim + b * NN * NN;
    const float* cmb  = g_cm  + b * NN * NN;

    // ---- load own rows (sim, cm) transposed ----
    for (int idx = t; idx < 8 * NN; idx += 128) {
        int rr = idx / NN, j = idx - rr * NN;
        r0T[j][rr] = simb[(i0 + rr) * NN + j];
        cwT[j][rr] = cmb [(i0 + rr) * NN + j];
    }
    if (t < 8) invn[t] = 1.0f / g_nat[b * NN + i0 + t];
    __syncthreads();

    // ---- hop1: f1[rr][k] = (sum_j sim[i,j]*sim[j,k]) / n_i ----
    if (t < NN) {
        float a0=0,a1=0,a2=0,a3=0,a4=0,a5=0,a6=0,a7=0;
        #pragma unroll 4
        for (int j = 0; j < NN; j++) {
            float sv = simb[j * NN + t];
            float4 lo = *(const float4*)&r0T[j][0];
            float4 hi = *(const float4*)&r0T[j][4];
            a0 = fmaf(lo.x, sv, a0); a1 = fmaf(lo.y, sv, a1);
            a2 = fmaf(lo.z, sv, a2); a3 = fmaf(lo.w, sv, a3);
            a4 = fmaf(hi.x, sv, a4); a5 = fmaf(hi.y, sv, a5);
            a6 = fmaf(hi.z, sv, a6); a7 = fmaf(hi.w, sv, a7);
        }
        r1T[t][0]=a0*invn[0]; r1T[t][1]=a1*invn[1]; r1T[t][2]=a2*invn[2]; r1T[t][3]=a3*invn[3];
        r1T[t][4]=a4*invn[4]; r1T[t][5]=a5*invn[5]; r1T[t][6]=a6*invn[6]; r1T[t][7]=a7*invn[7];
    }
    __syncthreads();

    // ---- hop2: f2[rr][k] = (sum_j f1[i,j]*sim[j,k]) / n_i ----
    if (t < NN) {
        float a0=0,a1=0,a2=0,a3=0,a4=0,a5=0,a6=0,a7=0;
        #pragma unroll 4
        for (int j = 0; j < NN; j++) {
            float sv = simb[j * NN + t];
            float4 lo = *(const float4*)&r1T[j][0];
            float4 hi = *(const float4*)&r1T[j][4];
            a0 = fmaf(lo.x, sv, a0); a1 = fmaf(lo.y, sv, a1);
            a2 = fmaf(lo.z, sv, a2); a3 = fmaf(lo.w, sv, a3);
            a4 = fmaf(hi.x, sv, a4); a5 = fmaf(hi.y, sv, a5);
            a6 = fmaf(hi.z, sv, a6); a7 = fmaf(hi.w, sv, a7);
        }
        r2T[t][0]=a0*invn[0]; r2T[t][1]=a1*invn[1]; r2T[t][2]=a2*invn[2]; r2T[t][3]=a3*invn[3];
        r2T[t][4]=a4*invn[4]; r2T[t][5]=a5*invn[5]; r2T[t][6]=a6*invn[6]; r2T[t][7]=a7*invn[7];
    }
    __syncthreads();

    // ---- compaction: 4 warps, 2 rows each, keep only cm != 0 ----
    {
        int lane = t & 31, w = t >> 5;
        for (int r = 2 * w; r < 2 * w + 2; r++) {
            int cnt = 0; float cs = 0.0f;
            #pragma unroll
            for (int ch = 0; ch < 3; ch++) {
                int j = ch * 32 + lane;
                float c = cwT[j][r];
                cs += c;
                bool p = (c != 0.0f);
                unsigned m = __ballot_sync(0xffffffffu, p);
                int pos = cnt + __popc(m & ((1u << lane) - 1u));
                if (p) packed[r][pos] = make_float4(r0T[j][r], r1T[j][r], r2T[j][r], c * LN2f);
                cnt += __popc(m);
            }
            #pragma unroll
            for (int o = 16; o > 0; o >>= 1) cs += __shfl_down_sync(0xffffffffu, cs, o);
            if (lane == 0) { cnt_s[r] = cnt; csum_s[r] = cs; }
        }
    }
    __syncthreads();
    if (t < 8) g_csum[b * NN + i0 + t] = csum_s[t];

    // ---- accS in log2 domain: ssp(z) = ln2*(max(t,0) + log2((1+2^-|t|)/2)), t=z*log2e ----
    int f = t;
    float w0 = fw1[f]        * LOG2Ef;
    float w1 = fw1[FF + f]   * LOG2Ef;
    float w2 = fw1[2*FF + f] * LOG2Ef;
    float b1 = fb1[f]        * LOG2Ef;
    #pragma unroll
    for (int rr = 0; rr < 8; rr++) {
        int cnt = cnt_s[rr];
        float acc = 0.0f;
        for (int jj = 0; jj < cnt; jj++) {
            float4 p = packed[rr][jj];
            float tt = fmaf(p.z, w2, fmaf(p.y, w1, fmaf(p.x, w0, b1)));
            float u;  asm("ex2.approx.f32 %0, %1;" : "=f"(u)  : "f"(-fabsf(tt)));
            float v = fmaf(u, 0.5f, 0.5f);
            float lg; asm("lg2.approx.f32 %0, %1;" : "=f"(lg) : "f"(v));
            acc = fmaf(p.w, fmaxf(tt, 0.0f) + lg, acc);
        }
        g_A[(b * NN + i0 + rr) * FF + f] = acc;
    }
}

// ================= K2: fused triple GEMM =================
// Per 16-row block:
//   ypre = x @ W_in2f                         (stays in sY)
//   t    = (A @ fw2 + fb2*csum[row]) * ypre   (stays in sIn)
//   out  = ssp(t @ W_out + b_out)             (STG)
// Thread tile: 2 rows x 4 cols, weights staged 32 rows at a time.
__global__ __launch_bounds__(256) void k_mega(const float* __restrict__ x,
                                              const float* __restrict__ Win,
                                              const float* __restrict__ fw2,
                                              const float* __restrict__ fb2,
                                              const float* __restrict__ Wout,
                                              const float* __restrict__ bout,
                                              float* __restrict__ out) {
    __shared__ __align__(16) float sW [32 * FF];
    __shared__ __align__(16) float sIn[16 * FF];
    __shared__ __align__(16) float sY [16 * FF];
    int row0 = blockIdx.x * 16;
    int t    = threadIdx.x;                 // 0..255
    int c0   = (t & 31) * 4;                // 4 contiguous cols
    int r0   = (t >> 5) * 2;                // 2 rows

    // load x rows
    for (int i = t; i < 16 * FF / 4; i += 256)
        ((float4*)sIn)[i] = ((const float4*)(x + row0 * FF))[i];

    float acc[2][4];

    // ---------- GEMM1: ypre = x @ W_in2f ----------
    #pragma unroll
    for (int i = 0; i < 2; i++)
        #pragma unroll
        for (int q = 0; q < 4; q++) acc[i][q] = 0.0f;
    for (int kb = 0; kb < FF; kb += 32) {
        __syncthreads();
        for (int i = t; i < 32 * FF / 4; i += 256)
            ((float4*)sW)[i] = ((const float4*)(Win + kb * FF))[i];
        __syncthreads();
        #pragma unroll 8
        for (int kk = 0; kk < 32; kk++) {
            float4 wv = *(const float4*)&sW[kk * FF + c0];
            float a0 = sIn[r0 * FF + kb + kk];
            float a1 = sIn[(r0 + 1) * FF + kb + kk];
            acc[0][0]=fmaf(a0,wv.x,acc[0][0]); acc[0][1]=fmaf(a0,wv.y,acc[0][1]);
            acc[0][2]=fmaf(a0,wv.z,acc[0][2]); acc[0][3]=fmaf(a0,wv.w,acc[0][3]);
            acc[1][0]=fmaf(a1,wv.x,acc[1][0]); acc[1][1]=fmaf(a1,wv.y,acc[1][1]);
            acc[1][2]=fmaf(a1,wv.z,acc[1][2]); acc[1][3]=fmaf(a1,wv.w,acc[1][3]);
        }
    }
    __syncthreads();   // everyone done reading sIn (x)
    *(float4*)&sY[r0 * FF + c0]       = make_float4(acc[0][0], acc[0][1], acc[0][2], acc[0][3]);
    *(float4*)&sY[(r0 + 1) * FF + c0] = make_float4(acc[1][0], acc[1][1], acc[1][2], acc[1][3]);
    // load A rows (overwrite sIn)
    for (int i = t; i < 16 * FF / 4; i += 256)
        ((float4*)sIn)[i] = ((const float4*)(g_A + row0 * FF))[i];

    // ---------- GEMM2: t = A @ fw2 ----------
    #pragma unroll
    for (int i = 0; i < 2; i++)
        #pragma unroll
        for (int q = 0; q < 4; q++) acc[i][q] = 0.0f;
    for (int kb = 0; kb < FF; kb += 32) {
        __syncthreads();
        for (int i = t; i < 32 * FF / 4; i += 256)
            ((float4*)sW)[i] = ((const float4*)(fw2 + kb * FF))[i];
        __syncthreads();
        #pragma unroll 8
        for (int kk = 0; kk < 32; kk++) {
            float4 wv = *(const float4*)&sW[kk * FF + c0];
            float a0 = sIn[r0 * FF + kb + kk];
            float a1 = sIn[(r0 + 1) * FF + kb + kk];
            acc[0][0]=fmaf(a0,wv.x,acc[0][0]); acc[0][1]=fmaf(a0,wv.y,acc[0][1]);
            acc[0][2]=fmaf(a0,wv.z,acc[0][2]); acc[0][3]=fmaf(a0,wv.w,acc[0][3]);
            acc[1][0]=fmaf(a1,wv.x,acc[1][0]); acc[1][1]=fmaf(a1,wv.y,acc[1][1]);
            acc[1][2]=fmaf(a1,wv.z,acc[1][2]); acc[1][3]=fmaf(a1,wv.w,acc[1][3]);
        }
    }
    __syncthreads();   // everyone done reading sIn (A)
    {   // epilogue2: (t + fb2*csum) * ypre  -> sIn
        float cs0 = g_csum[row0 + r0], cs1 = g_csum[row0 + r0 + 1];
        float4 fb = *(const float4*)&fb2[c0];
        float4 y0 = *(const float4*)&sY[r0 * FF + c0];
        float4 y1 = *(const float4*)&sY[(r0 + 1) * FF + c0];
        float4 o0, o1;
        o0.x = fmaf(fb.x, cs0, acc[0][0]) * y0.x;  o0.y = fmaf(fb.y, cs0, acc[0][1]) * y0.y;
        o0.z = fmaf(fb.z, cs0, acc[0][2]) * y0.z;  o0.w = fmaf(fb.w, cs0, acc[0][3]) * y0.w;
        o1.x = fmaf(fb.x, cs1, acc[1][0]) * y1.x;  o1.y = fmaf(fb.y, cs1, acc[1][1]) * y1.y;
        o1.z = fmaf(fb.z, cs1, acc[1][2]) * y1.z;  o1.w = fmaf(fb.w, cs1, acc[1][3]) * y1.w;
        *(float4*)&sIn[r0 * FF + c0]       = o0;
        *(float4*)&sIn[(r0 + 1) * FF + c0] = o1;
    }

    // ---------- GEMM3: out = ssp(t @ W_out + b_out) ----------
    #pragma unroll
    for (int i = 0; i < 2; i++)
        #pragma unroll
        for (int q = 0; q < 4; q++) acc[i][q] = 0.0f;
    for (int kb = 0; kb < FF; kb += 32) {
        __syncthreads();   // also orders epilogue-2 STS before reads
        for (int i = t; i < 32 * FF / 4; i += 256)
            ((float4*)sW)[i] = ((const float4*)(Wout + kb * FF))[i];
        __syncthreads();
        #pragma unroll 8
        for (int kk = 0; kk < 32; kk++) {
            float4 wv = *(const float4*)&sW[kk * FF + c0];
            float a0 = sIn[r0 * FF + kb + kk];
            float a1 = sIn[(r0 + 1) * FF + kb + kk];
            acc[0][0]=fmaf(a0,wv.x,acc[0][0]); acc[0][1]=fmaf(a0,wv.y,acc[0][1]);
            acc[0][2]=fmaf(a0,wv.z,acc[0][2]); acc[0][3]=fmaf(a0,wv.w,acc[0][3]);
            acc[1][0]=fmaf(a1,wv.x,acc[1][0]); acc[1][1]=fmaf(a1,wv.y,acc[1][1]);
            acc[1][2]=fmaf(a1,wv.z,acc[1][2]); acc[1][3]=fmaf(a1,wv.w,acc[1][3]);
        }
    }
    {   // epilogue3: shifted softplus, STG
        float4 bo = *(const float4*)&bout[c0];
        float bz[4] = {bo.x, bo.y, bo.z, bo.w};
        #pragma unroll
        for (int i = 0; i < 2; i++) {
            float4 o;
            float* op = (float*)&o;
            #pragma unroll
            for (int q = 0; q < 4; q++) {
                float v = acc[i][q] + bz[q];
                float e = expf(-fabsf(v));
                op[q] = fmaxf(v, 0.0f) + log1pf(e) - LN2f;
            }
            *(float4*)&out[(row0 + r0 + i) * FF + c0] = o;
        }
    }
}

// ================= launch =================
extern "C" void kernel_launch(void* const* d_in, const int* in_sizes, int n_in,
                              void* d_out, int out_size) {
    const float* x      = (const float*)d_in[0];
    const float* r      = (const float*)d_in[1];
    // d_in[2] = neighbors (unused by this forward variant)
    const float* mask   = (const float*)d_in[3];
    const float* W_in2f = (const float*)d_in[4];
    const float* fw1    = (const float*)d_in[5];
    const float* fb1    = (const float*)d_in[6];
    const float* fw2    = (const float*)d_in[7];
    const float* fb2    = (const float*)d_in[8];
    const float* W_out  = (const float*)d_in[9];
    const float* b_out  = (const float*)d_in[10];
    float* out = (float*)d_out;

    k_prep  <<<NBI, NN>>>(r, mask);
    k_hopacc<<<BB * (NN / 8), 128>>>(fw1, fb1);
    k_mega  <<<NBI / 16, 256>>>(x, W_in2f, fw2, fb2, W_out, b_out, out);
}

// round 3
// speedup vs baseline: 1.3786x; 1.1088x over previous
#include <cuda_runtime.h>
#include <math.h>

#define BB 32
#define NN 96
#define FF 128
#define RPB 8
#define NBLK (BB*(NN/RPB))      // 384
#define THREADS 256
#define LN2f   0.69314718055994530942f
#define LOG2Ef 1.44269504088896340736f
#define PI_5   0.62831853071795864769f

// ---- float offsets into dynamic shared (peak 14592 floats = 58368 B) ----
#define OFF_SIM   0      // sim tile 96*96 (dead after compaction)
#define OFF_SA    0      // A[8][128]          (overlay, live from accS)
#define OFF_SPART 1024   // accS partials [8][128]
#define OFF_SX    2048   // x rows / t2 rows [8][128]
#define OFF_SW    4096   // weight chunk 32*128
#define OFF_PACK  9216   // compacted float4[8][96] -> 3072 floats
#define OFF_R0T   12288  // sim own-rows transposed [96][8]
#define OFF_R1T   13056
#define OFF_R2T   13824
#define SMEM_BYTES (14592*4)

extern __shared__ float sm[];

// acc4 = sIn[row,:] @ Wg[:, c0..c0+3], staging Wg in sW 32 rows at a time.
__device__ __forceinline__ float4 gemm_rowcols(const float* __restrict__ Wg,
                                               const float* sIn, float* sW,
                                               int row, int c0, int t) {
    float a0=0.f, a1=0.f, a2=0.f, a3=0.f;
    for (int kb = 0; kb < FF; kb += 32) {
        __syncthreads();
        for (int i = t; i < 32*FF/4; i += THREADS)
            ((float4*)sW)[i] = ((const float4*)(Wg + kb*FF))[i];
        __syncthreads();
        #pragma unroll 8
        for (int kk = 0; kk < 32; kk++) {
            float  av = sIn[row*FF + kb + kk];
            float4 wv = *(const float4*)&sW[kk*FF + c0];
            a0 = fmaf(av, wv.x, a0); a1 = fmaf(av, wv.y, a1);
            a2 = fmaf(av, wv.z, a2); a3 = fmaf(av, wv.w, a3);
        }
    }
    return make_float4(a0, a1, a2, a3);
}

__global__ __launch_bounds__(THREADS) void k_fused(
    const float* __restrict__ x,    const float* __restrict__ r,
    const float* __restrict__ mask, const float* __restrict__ Win,
    const float* __restrict__ fw1,  const float* __restrict__ fb1,
    const float* __restrict__ fw2,  const float* __restrict__ fb2,
    const float* __restrict__ Wout, const float* __restrict__ bout,
    float* __restrict__ out)
{
    __shared__ float invn_s[RPB], csum_s[RPB];
    __shared__ int   cnt_s[RPB];

    const int b  = blockIdx.x / (NN/RPB);
    const int i0 = (blockIdx.x % (NN/RPB)) * RPB;
    const int t  = threadIdx.x;
    const size_t bbase = (size_t)b * NN * NN;

    // ---- 1. sim tile in shared: sim[i][j] = exp(-r)*mask ----
    for (int idx = t; idx < NN*NN; idx += THREADS) {
        float rv = r[bbase + idx];
        float m  = mask[bbase + idx];
        sm[OFF_SIM + idx] = __expf(-rv) * m;
    }
    __syncthreads();

    // ---- 2. n_atoms for own rows (sim==0 <=> mask==0; exp(-r) >= e^-8 > 0) ----
    {
        int w = t >> 5, lane = t & 31;   // warp w owns row i0+w
        int n = 0;
        #pragma unroll
        for (int ch = 0; ch < 3; ch++) {
            bool nz = sm[OFF_SIM + (i0+w)*NN + ch*32 + lane] != 0.0f;
            n += __popc(__ballot_sync(0xffffffffu, nz));
        }
        if (lane == 0) invn_s[w] = 1.0f / fmaxf((float)n, 1.0f);
    }
    // ---- 3. own sim rows transposed: r0T[j][rr] ----
    for (int idx = t; idx < RPB*NN; idx += THREADS) {
        int rr = idx / NN, j = idx - rr*NN;
        sm[OFF_R0T + j*RPB + rr] = sm[OFF_SIM + (i0+rr)*NN + j];
    }
    __syncthreads();

    // ---- 4. hop1: f1[i,k] = sum_j sim[i,j]*sim[j,k] / n_i  (192 threads: 2 groups x 4 rows) ----
    if (t < 2*NN) {
        int gr = (t >= NN), col = t - NN*gr, rb = gr*4;
        float a0=0.f,a1=0.f,a2=0.f,a3=0.f;
        #pragma unroll 8
        for (int j = 0; j < NN; j++) {
            float  sv = sm[OFF_SIM + j*NN + col];
            float4 rv = *(const float4*)&sm[OFF_R0T + j*RPB + rb];
            a0 = fmaf(rv.x, sv, a0); a1 = fmaf(rv.y, sv, a1);
            a2 = fmaf(rv.z, sv, a2); a3 = fmaf(rv.w, sv, a3);
        }
        *(float4*)&sm[OFF_R1T + col*RPB + rb] =
            make_float4(a0*invn_s[rb], a1*invn_s[rb+1], a2*invn_s[rb+2], a3*invn_s[rb+3]);
    }
    __syncthreads();

    // ---- 5. hop2: f2 = (f1 @ sim) / n ----
    if (t < 2*NN) {
        int gr = (t >= NN), col = t - NN*gr, rb = gr*4;
        float a0=0.f,a1=0.f,a2=0.f,a3=0.f;
        #pragma unroll 8
        for (int j = 0; j < NN; j++) {
            float  sv = sm[OFF_SIM + j*NN + col];
            float4 rv = *(const float4*)&sm[OFF_R1T + j*RPB + rb];
            a0 = fmaf(rv.x, sv, a0); a1 = fmaf(rv.y, sv, a1);
            a2 = fmaf(rv.z, sv, a2); a3 = fmaf(rv.w, sv, a3);
        }
        *(float4*)&sm[OFF_R2T + col*RPB + rb] =
            make_float4(a0*invn_s[rb], a1*invn_s[rb+1], a2*invn_s[rb+2], a3*invn_s[rb+3]);
    }
    __syncthreads();

    // ---- 6. compaction: warp w compacts row i0+w (keep cm != 0) ----
    {
        int w = t >> 5, lane = t & 31;
        float4* pk = (float4*)&sm[OFF_PACK];
        int cnt = 0; float cs = 0.0f;
        #pragma unroll
        for (int ch = 0; ch < 3; ch++) {
            int   j  = ch*32 + lane;
            float s0 = sm[OFF_SIM + (i0+w)*NN + j];
            float rv = r[bbase + (size_t)(i0+w)*NN + j];
            float c  = 0.0f;
            if (rv < 5.0f && s0 != 0.0f)
                c = 0.5f * (__cosf(rv * PI_5) + 1.0f);
            cs += c;
            bool p = (c != 0.0f);
            unsigned bm = __ballot_sync(0xffffffffu, p);
            int pos = cnt + __popc(bm & ((1u << lane) - 1u));
            if (p)
                pk[w*NN + pos] = make_float4(s0, sm[OFF_R1T + j*RPB + w],
                                             sm[OFF_R2T + j*RPB + w], c * LN2f);
            cnt += __popc(bm);
        }
        #pragma unroll
        for (int o = 16; o > 0; o >>= 1) cs += __shfl_down_sync(0xffffffffu, cs, o);
        if (lane == 0) { cnt_s[w] = cnt; csum_s[w] = cs; }
    }
    __syncthreads();

    // ---- 7. accS (log2 domain), j-loop split across two 128-thread halves ----
    {
        int f = t & (FF-1), h = t >> 7;
        float w0 = fw1[f]        * LOG2Ef;
        float w1 = fw1[FF + f]   * LOG2Ef;
        float w2 = fw1[2*FF + f] * LOG2Ef;
        float b1 = fb1[f]        * LOG2Ef;
        const float4* pk = (const float4*)&sm[OFF_PACK];
        float accv[RPB];
        #pragma unroll
        for (int rr = 0; rr < RPB; rr++) {
            int cnt  = cnt_s[rr];
            int half = (cnt + 1) >> 1;
            int jb   = h ? half : 0;
            int je   = h ? cnt  : half;
            float a = 0.0f;
            for (int jj = jb; jj < je; jj++) {
                float4 p  = pk[rr*NN + jj];
                float  tt = fmaf(p.z, w2, fmaf(p.y, w1, fmaf(p.x, w0, b1)));
                float  u;  asm("ex2.approx.f32 %0, %1;" : "=f"(u)  : "f"(-fabsf(tt)));
                float  v  = fmaf(u, 0.5f, 0.5f);
                float  lg; asm("lg2.approx.f32 %0, %1;" : "=f"(lg) : "f"(v));
                a = fmaf(p.w, fmaxf(tt, 0.0f) + lg, a);
            }
            accv[rr] = a;
        }
        if (h) {
            #pragma unroll
            for (int rr = 0; rr < RPB; rr++) sm[OFF_SPART + rr*FF + f] = accv[rr];
        }
        __syncthreads();   // sim region now dead; sA overlay safe
        if (!h) {
            #pragma unroll
            for (int rr = 0; rr < RPB; rr++)
                sm[OFF_SA + rr*FF + f] = accv[rr] + sm[OFF_SPART + rr*FF + f];
        }
    }
    // (visibility of sA / sX handled by the sync at the top of gemm_rowcols)

    // ---- 8. GEMM chain on own 8 rows ----
    const int row = t >> 5;               // 0..7
    const int c0  = (t & 31) * 4;         // 4 contiguous cols
    // load x rows
    for (int i = t; i < RPB*FF/4; i += THREADS)
        ((float4*)&sm[OFF_SX])[i] = ((const float4*)(x + (size_t)(b*NN + i0)*FF))[i];

    // GEMM1: ypre stays in registers (this thread's slot == its epilogue-2 slot)
    float4 yp = gemm_rowcols(Win, &sm[OFF_SX], &sm[OFF_SW], row, c0, t);

    // GEMM2: t2 = (A @ fw2 + fb2*csum) * ypre  -> sT (reuse OFF_SX)
    float4 t2 = gemm_rowcols(fw2, &sm[OFF_SA], &sm[OFF_SW], row, c0, t);
    {
        float  cs = csum_s[row];
        float4 fb = *(const float4*)&fb2[c0];
        float4 o;
        o.x = fmaf(fb.x, cs, t2.x) * yp.x;  o.y = fmaf(fb.y, cs, t2.y) * yp.y;
        o.z = fmaf(fb.z, cs, t2.z) * yp.z;  o.w = fmaf(fb.w, cs, t2.w) * yp.w;
        *(float4*)&sm[OFF_SX + row*FF + c0] = o;
    }

    // GEMM3: out = ssp(t2 @ Wout + bout)
    float4 t3 = gemm_rowcols(Wout, &sm[OFF_SX], &sm[OFF_SW], row, c0, t);
    {
        float4 bo = *(const float4*)&bout[c0];
        float  vin[4] = { t3.x + bo.x, t3.y + bo.y, t3.z + bo.z, t3.w + bo.w };
        float4 o; float* op = (float*)&o;
        #pragma unroll
        for (int q = 0; q < 4; q++) {
            float u = vin[q] * LOG2Ef;
            float e;  asm("ex2.approx.f32 %0, %1;" : "=f"(e)  : "f"(-fabsf(u)));
            float v = fmaf(e, 0.5f, 0.5f);
            float lg; asm("lg2.approx.f32 %0, %1;" : "=f"(lg) : "f"(v));
            op[q] = LN2f * (fmaxf(u, 0.0f) + lg);
        }
        *(float4*)&out[(size_t)(b*NN + i0 + row)*FF + c0] = o;
    }
}

// ================= launch =================
extern "C" void kernel_launch(void* const* d_in, const int* in_sizes, int n_in,
                              void* d_out, int out_size) {
    const float* x      = (const float*)d_in[0];
    const float* r      = (const float*)d_in[1];
    // d_in[2] = neighbors (unused by this forward variant)
    const float* mask   = (const float*)d_in[3];
    const float* W_in2f = (const float*)d_in[4];
    const float* fw1    = (const float*)d_in[5];
    const float* fb1    = (const float*)d_in[6];
    const float* fw2    = (const float*)d_in[7];
    const float* fb2    = (const float*)d_in[8];
    const float* W_out  = (const float*)d_in[9];
    const float* b_out  = (const float*)d_in[10];
    float* out = (float*)d_out;

    static bool attr_set = false;
    if (!attr_set) {
        cudaFuncSetAttribute(k_fused, cudaFuncAttributeMaxDynamicSharedMemorySize, SMEM_BYTES);
        attr_set = true;
    }
    k_fused<<<NBLK, THREADS, SMEM_BYTES>>>(x, r, mask, W_in2f, fw1, fb1, fw2, fb2,
                                           W_out, b_out, out);
}